// round 8
// baseline (speedup 1.0000x reference)
#include <cuda_runtime.h>
#include <cstdint>

#define N0 900000
#define N1C 43008
#define N2C 2048
#define D 64
#define TWO_D 128
#define CAP 96
#define CAP1 16
#define WSTRIDE 132
#define INSTRIDE 132
#define NCHUNK 4
#define CHUNK_T (N1C / NCHUNK)          // 10752 targets per chunk
#define CHUNK_B (CHUNK_T / 128)         // 84 gemm blocks per chunk
#define HSTRIDE 68

// ---------------- device-global scratch ------------------------------------
__device__ float g_agg0[N1C * D];
__device__ float g_h1[N2C * D];          // only rows < N2C ever needed
__device__ float g_agg1[N2C * D];        // zero-invariant: gemm1 restores
__device__ int   g_cnti[N1C + N2C];      // c0 | c1(dst counts); restored in-kernel
__device__ int   g_c1s[N1C];             // L1 out-degree by src; gemm0 restores
__device__ int   g_slots0[N1C * CAP];
__device__ int   g_slots1s[N1C * CAP1];  // L1 dst lists by src

// ---------------- build: L0 slots(dst) + L1 counts(dst) + L1 slots(src) -----
__global__ void fill3_kernel(const int* __restrict__ es0, const int* __restrict__ ed0,
                             int* __restrict__ c0, int* __restrict__ sl0,
                             const int* __restrict__ es1, const int* __restrict__ ed1,
                             int* __restrict__ c1, int* __restrict__ c1s,
                             int* __restrict__ sl1s,
                             int E0, int E1) {
    int e = blockIdx.x * blockDim.x + threadIdx.x;
    if (e < E0) {
        int d = ed0[e];
        int p = atomicAdd(&c0[d], 1);
        if (p < CAP) sl0[d * CAP + p] = es0[e];
    } else if (e < E0 + E1) {
        atomicAdd(&c1[ed1[e - E0]], 1);
    } else if (e < E0 + 2 * E1) {
        int i = e - E0 - E1;
        int s = es1[i];
        int p = atomicAdd(&c1s[s], 1);
        if (p < CAP1) sl1s[s * CAP1 + p] = ed1[i];
    }
}

// ---------------- layer-0 gather + mean (16 lanes/target, chunked) ----------
__global__ void gather_mean_kernel(const float* __restrict__ src_feat,
                                   const int* __restrict__ slots,
                                   int* __restrict__ cnti,
                                   float* __restrict__ agg, int g0, int gend) {
    int t = blockIdx.x * blockDim.x + threadIdx.x;
    int g = g0 + (t >> 4);
    if (g >= gend) return;
    int l = t & 15;
    int deg = cnti[g];
    int m = min(deg, CAP);
    const int* sl = slots + (size_t)g * CAP;
    const float4* base = reinterpret_cast<const float4*>(src_feat);
    float4 acc = make_float4(0.f, 0.f, 0.f, 0.f);
    int e = 0;
    for (; e + 8 <= m; e += 8) {
        int4 ia = *reinterpret_cast<const int4*>(sl + e);
        int4 ib = *reinterpret_cast<const int4*>(sl + e + 4);
        float4 v0 = base[(size_t)ia.x * 16 + l];
        float4 v1 = base[(size_t)ia.y * 16 + l];
        float4 v2 = base[(size_t)ia.z * 16 + l];
        float4 v3 = base[(size_t)ia.w * 16 + l];
        float4 v4 = base[(size_t)ib.x * 16 + l];
        float4 v5 = base[(size_t)ib.y * 16 + l];
        float4 v6 = base[(size_t)ib.z * 16 + l];
        float4 v7 = base[(size_t)ib.w * 16 + l];
        acc.x += ((v0.x + v1.x) + (v2.x + v3.x)) + ((v4.x + v5.x) + (v6.x + v7.x));
        acc.y += ((v0.y + v1.y) + (v2.y + v3.y)) + ((v4.y + v5.y) + (v6.y + v7.y));
        acc.z += ((v0.z + v1.z) + (v2.z + v3.z)) + ((v4.z + v5.z) + (v6.z + v7.z));
        acc.w += ((v0.w + v1.w) + (v2.w + v3.w)) + ((v4.w + v5.w) + (v6.w + v7.w));
    }
    for (; e < m; e++) {
        float4 v = base[(size_t)sl[e] * 16 + l];
        acc.x += v.x; acc.y += v.y; acc.z += v.z; acc.w += v.w;
    }
    float scl = 1.0f / fmaxf((float)deg, 1.0f);
    acc.x *= scl; acc.y *= scl; acc.z *= scl; acc.w *= scl;
    reinterpret_cast<float4*>(agg)[(size_t)g * 16 + l] = acc;
    if (l == 0) cnti[g] = 0;
}

// ---------------- tf32 helpers ----------------------------------------------
__device__ __forceinline__ uint32_t f2tf32(float f) {
    uint32_t u;
    asm("cvt.rna.tf32.f32 %0, %1;" : "=r"(u) : "f"(f));
    return u;
}

__device__ __forceinline__ void mma_tf32(float* c, uint32_t a0, uint32_t a1,
                                         uint32_t a2, uint32_t a3,
                                         uint32_t b0, uint32_t b1) {
    asm volatile("mma.sync.aligned.m16n8k8.row.col.f32.tf32.tf32.f32 "
                 "{%0,%1,%2,%3}, {%4,%5,%6,%7}, {%8,%9}, {%0,%1,%2,%3};"
                 : "+f"(c[0]), "+f"(c[1]), "+f"(c[2]), "+f"(c[3])
                 : "r"(a0), "r"(a1), "r"(a2), "r"(a3), "r"(b0), "r"(b1));
}

// ---------------- gemm0: [x|agg0] @ W0 + b0, relu, fused L1 scatter ---------
// 128 rows/CTA, 256 threads. Stores h1 only for rows < N2C; scatters every
// row's outgoing L1 edges into agg1 via red.global. Resets c1s.
__global__ void __launch_bounds__(256)
sage_gemm0(const float* __restrict__ self_feat,
           const float* __restrict__ agg,
           const float* __restrict__ w, const float* __restrict__ b,
           float* __restrict__ h1out,
           int* __restrict__ c1s, const int* __restrict__ sl1s,
           float* __restrict__ agg1, int cbase) {
    extern __shared__ uint32_t smu[];
    uint32_t* wsh  = smu;                  // W^T tf32: [64][WSTRIDE]
    uint32_t* insh = smu + D * WSTRIDE;    // A tf32:   [128][INSTRIDE]
    float* hsh = reinterpret_cast<float*>(insh);   // reused after MMA

    const int tid  = threadIdx.x;
    const int wid  = tid >> 5;
    const int lane = tid & 31;
    const int gid  = lane >> 2;
    const int qid  = lane & 3;
    const int row0 = (cbase + blockIdx.x) * 128;

    for (int i = tid; i < TWO_D * 16; i += 256) {
        int k = i >> 4;
        int l = i & 15;
        float4 v = reinterpret_cast<const float4*>(w)[i];
        wsh[(l * 4 + 0) * WSTRIDE + k] = f2tf32(v.x);
        wsh[(l * 4 + 1) * WSTRIDE + k] = f2tf32(v.y);
        wsh[(l * 4 + 2) * WSTRIDE + k] = f2tf32(v.z);
        wsh[(l * 4 + 3) * WSTRIDE + k] = f2tf32(v.w);
    }

    const float4* sbase = reinterpret_cast<const float4*>(self_feat);
    const float4* abase = reinterpret_cast<const float4*>(agg);
    for (int i = tid; i < 128 * 16; i += 256) {
        int r = i >> 4;
        int l = i & 15;
        size_t gi = (size_t)(row0 + r) * 16 + l;
        float4 s = sbase[gi];
        float4 a = abase[gi];
        uint32_t* dst = insh + r * INSTRIDE + l * 4;
        dst[0] = f2tf32(s.x); dst[1] = f2tf32(s.y);
        dst[2] = f2tf32(s.z); dst[3] = f2tf32(s.w);
        uint32_t* dst2 = dst + D;
        dst2[0] = f2tf32(a.x); dst2[1] = f2tf32(a.y);
        dst2[2] = f2tf32(a.z); dst2[3] = f2tf32(a.w);
    }
    __syncthreads();

    const uint32_t* a_base = insh + (wid * 16 + gid) * INSTRIDE + qid;
    const uint32_t* b_base = wsh + gid * WSTRIDE + qid;

    float c[8][4] = {};
    #pragma unroll
    for (int k0 = 0; k0 < TWO_D; k0 += 8) {
        uint32_t a0 = a_base[k0];
        uint32_t a1 = a_base[8 * INSTRIDE + k0];
        uint32_t a2 = a_base[k0 + 4];
        uint32_t a3 = a_base[8 * INSTRIDE + k0 + 4];
        #pragma unroll
        for (int nt = 0; nt < 8; nt++) {
            uint32_t b0 = b_base[nt * 8 * WSTRIDE + k0];
            uint32_t b1 = b_base[nt * 8 * WSTRIDE + k0 + 4];
            mma_tf32(c[nt], a0, a1, a2, a3, b0, b1);
        }
    }
    __syncthreads();   // A-tile reads done; insh reusable as hsh

    // epilogue: bias + relu; write h tile to smem; store rows < N2C to gmem
    int rloc = wid * 16 + gid;
    int row = row0 + rloc;
    #pragma unroll
    for (int nt = 0; nt < 8; nt++) {
        int col = nt * 8 + qid * 2;
        float2 bv = *reinterpret_cast<const float2*>(b + col);
        float2 r01 = make_float2(fmaxf(c[nt][0] + bv.x, 0.f),
                                 fmaxf(c[nt][1] + bv.y, 0.f));
        float2 r23 = make_float2(fmaxf(c[nt][2] + bv.x, 0.f),
                                 fmaxf(c[nt][3] + bv.y, 0.f));
        *reinterpret_cast<float2*>(hsh + rloc * HSTRIDE + col) = r01;
        *reinterpret_cast<float2*>(hsh + (rloc + 8) * HSTRIDE + col) = r23;
        if (row < N2C)
            *reinterpret_cast<float2*>(h1out + (size_t)row * D + col) = r01;
        if (row + 8 < N2C)
            *reinterpret_cast<float2*>(h1out + (size_t)(row + 8) * D + col) = r23;
    }
    __syncthreads();

    // fused L1 scatter: warp owns rows wid*16 .. +15; 2 edges per pass
    const int sub = lane >> 4;
    const int l = lane & 15;
    for (int j = 0; j < 16; j++) {
        int r = wid * 16 + j;
        int R = row0 + r;
        int deg = min(c1s[R], CAP1);
        const float4 v = *reinterpret_cast<const float4*>(hsh + r * HSTRIDE + l * 4);
        for (int e = sub; e < deg; e += 2) {
            int d = sl1s[R * CAP1 + e];
            float* dst = agg1 + (size_t)d * D + l * 4;
            asm volatile("red.global.add.v4.f32 [%0], {%1,%2,%3,%4};"
                         :: "l"(dst), "f"(v.x), "f"(v.y), "f"(v.z), "f"(v.w)
                         : "memory");
        }
        if (lane == 0) c1s[R] = 0;   // restore invariant
    }
}

// ---------------- gemm1: [h1|agg1/c1] @ W1 + b1; restores agg1/c1 zeros -----
__global__ void __launch_bounds__(256)
sage_gemm1(const float* __restrict__ self_feat,
           float* __restrict__ agg, int* __restrict__ cnti,
           const float* __restrict__ w, const float* __restrict__ b,
           float* __restrict__ out) {
    extern __shared__ uint32_t smu[];
    uint32_t* wsh  = smu;
    uint32_t* insh = smu + D * WSTRIDE;

    const int tid  = threadIdx.x;
    const int wid  = tid >> 5;
    const int lane = tid & 31;
    const int gid  = lane >> 2;
    const int qid  = lane & 3;
    const int row0 = blockIdx.x * 128;

    for (int i = tid; i < TWO_D * 16; i += 256) {
        int k = i >> 4;
        int l = i & 15;
        float4 v = reinterpret_cast<const float4*>(w)[i];
        wsh[(l * 4 + 0) * WSTRIDE + k] = f2tf32(v.x);
        wsh[(l * 4 + 1) * WSTRIDE + k] = f2tf32(v.y);
        wsh[(l * 4 + 2) * WSTRIDE + k] = f2tf32(v.z);
        wsh[(l * 4 + 3) * WSTRIDE + k] = f2tf32(v.w);
    }

    const float4* sbase = reinterpret_cast<const float4*>(self_feat);
    float4* abase = reinterpret_cast<float4*>(agg);
    for (int i = tid; i < 128 * 16; i += 256) {
        int r = i >> 4;
        int l = i & 15;
        int row = row0 + r;
        size_t gi = (size_t)row * 16 + l;
        float4 s = sbase[gi];
        float4 a = abase[gi];
        float scl = 1.0f / fmaxf((float)cnti[row], 1.0f);
        a.x *= scl; a.y *= scl; a.z *= scl; a.w *= scl;
        uint32_t* dst = insh + r * INSTRIDE + l * 4;
        dst[0] = f2tf32(s.x); dst[1] = f2tf32(s.y);
        dst[2] = f2tf32(s.z); dst[3] = f2tf32(s.w);
        uint32_t* dst2 = dst + D;
        dst2[0] = f2tf32(a.x); dst2[1] = f2tf32(a.y);
        dst2[2] = f2tf32(a.z); dst2[3] = f2tf32(a.w);
    }
    __syncthreads();

    // restore zero-invariants (reads completed above)
    for (int i = tid; i < 128 * 16; i += 256) {
        int r = i >> 4;
        int l = i & 15;
        abase[(size_t)(row0 + r) * 16 + l] = make_float4(0.f, 0.f, 0.f, 0.f);
    }
    if (tid < 128) cnti[row0 + tid] = 0;

    const uint32_t* a_base = insh + (wid * 16 + gid) * INSTRIDE + qid;
    const uint32_t* b_base = wsh + gid * WSTRIDE + qid;

    float c[8][4] = {};
    #pragma unroll
    for (int k0 = 0; k0 < TWO_D; k0 += 8) {
        uint32_t a0 = a_base[k0];
        uint32_t a1 = a_base[8 * INSTRIDE + k0];
        uint32_t a2 = a_base[k0 + 4];
        uint32_t a3 = a_base[8 * INSTRIDE + k0 + 4];
        #pragma unroll
        for (int nt = 0; nt < 8; nt++) {
            uint32_t b0 = b_base[nt * 8 * WSTRIDE + k0];
            uint32_t b1 = b_base[nt * 8 * WSTRIDE + k0 + 4];
            mma_tf32(c[nt], a0, a1, a2, a3, b0, b1);
        }
    }

    int row = row0 + wid * 16 + gid;
    #pragma unroll
    for (int nt = 0; nt < 8; nt++) {
        int col = nt * 8 + qid * 2;
        float2 bv = *reinterpret_cast<const float2*>(b + col);
        float2 r01 = make_float2(c[nt][0] + bv.x, c[nt][1] + bv.y);
        float2 r23 = make_float2(c[nt][2] + bv.x, c[nt][3] + bv.y);
        *reinterpret_cast<float2*>(out + (size_t)row * D + col) = r01;
        *reinterpret_cast<float2*>(out + (size_t)(row + 8) * D + col) = r23;
    }
}

static const int SMEM_MMA = (D * WSTRIDE + 128 * INSTRIDE) * (int)sizeof(uint32_t);

// ---------------- launch ---------------------------------------------------
extern "C" void kernel_launch(void* const* d_in, const int* in_sizes, int n_in,
                              void* d_out, int out_size) {
    const float* x         = (const float*)d_in[0];
    const float* w0        = (const float*)d_in[1];
    const float* b0        = (const float*)d_in[2];
    const float* w1        = (const float*)d_in[3];
    const float* b1        = (const float*)d_in[4];
    const int*   edge_src0 = (const int*)d_in[5];
    const int*   edge_dst0 = (const int*)d_in[6];
    const int*   edge_src1 = (const int*)d_in[7];
    const int*   edge_dst1 = (const int*)d_in[8];
    const int E0 = in_sizes[5];
    const int E1 = in_sizes[7];

    float *agg0, *h1, *agg1;
    int *cnti, *c1s, *slots0, *slots1s;
    cudaGetSymbolAddress((void**)&agg0,    g_agg0);
    cudaGetSymbolAddress((void**)&h1,      g_h1);
    cudaGetSymbolAddress((void**)&agg1,    g_agg1);
    cudaGetSymbolAddress((void**)&cnti,    g_cnti);
    cudaGetSymbolAddress((void**)&c1s,     g_c1s);
    cudaGetSymbolAddress((void**)&slots0,  g_slots0);
    cudaGetSymbolAddress((void**)&slots1s, g_slots1s);
    int* cnti0 = cnti;
    int* cnti1 = cnti + N1C;

    // one-time resources (created on the uncaptured correctness call)
    static cudaStream_t s1 = nullptr;
    static cudaEvent_t evA[NCHUNK];
    static cudaEvent_t evB = nullptr;
    if (s1 == nullptr) {
        cudaStreamCreateWithFlags(&s1, cudaStreamNonBlocking);
        for (int i = 0; i < NCHUNK; i++)
            cudaEventCreateWithFlags(&evA[i], cudaEventDisableTiming);
        cudaEventCreateWithFlags(&evB, cudaEventDisableTiming);
        cudaFuncSetAttribute(sage_gemm0,
                             cudaFuncAttributeMaxDynamicSharedMemorySize, SMEM_MMA);
        cudaFuncSetAttribute(sage_gemm1,
                             cudaFuncAttributeMaxDynamicSharedMemorySize, SMEM_MMA);
    }

    // build (all adjacency structures, one pass)
    int EB = E0 + 2 * E1;
    fill3_kernel<<<(EB + 255) / 256, 256>>>(edge_src0, edge_dst0, cnti0, slots0,
                                            edge_src1, edge_dst1, cnti1, c1s,
                                            slots1s, E0, E1);

    // pipelined layer 0: gather chunk i (stream 0) -> gemm0 chunk i (s1)
    for (int i = 0; i < NCHUNK; i++) {
        int g0 = i * CHUNK_T;
        gather_mean_kernel<<<CHUNK_T * 16 / 256, 256>>>(x, slots0, cnti0,
                                                        agg0, g0, g0 + CHUNK_T);
        cudaEventRecord(evA[i], 0);
        cudaStreamWaitEvent(s1, evA[i], 0);
        sage_gemm0<<<CHUNK_B, 256, SMEM_MMA, s1>>>(x, agg0, w0, b0, h1,
                                                   c1s, slots1s, agg1,
                                                   i * CHUNK_B);
    }
    cudaEventRecord(evB, s1);
    cudaStreamWaitEvent(0, evB, 0);

    // layer 1 GEMM
    sage_gemm1<<<N2C / 128, 256, SMEM_MMA>>>(h1, agg1, cnti1, w1, b1,
                                             (float*)d_out);
}

// round 9
// speedup vs baseline: 1.0722x; 1.0722x over previous
#include <cuda_runtime.h>
#include <cstdint>

#define N1C 43008
#define N2C 2048
#define D 64
#define TWO_D 128
#define CAP 96
#define CAP1 16
#define WSTRIDE 132
#define INSTRIDE 132
#define HSTRIDE 68
#define NTILES0 (N1C / 128)   // 336
#define NTILES1 (N2C / 128)   // 16

// ---------------- device-global scratch ------------------------------------
__device__ float g_agg0[N1C * D];
__device__ float g_h1[N2C * D];          // only rows < N2C consumed downstream
__device__ float g_agg1[N2C * D];        // zero-invariant (gemm1 restores)
__device__ int   g_cnti[N1C + N2C];      // c0 | c1 ; restored in-kernel
__device__ int   g_c1s[N1C];             // L1 out-degree by src; restored
__device__ int   g_slots0[N1C * CAP];
__device__ int   g_slots1s[N1C * CAP1];
__device__ unsigned g_bar_cnt = 0;       // barrier arrive counter
__device__ unsigned g_bar_gen = 0;       // barrier generation (monotonic)

// ---------------- software grid barrier -------------------------------------
__device__ __forceinline__ void grid_barrier(unsigned nblocks) {
    __syncthreads();
    if (threadIdx.x == 0) {
        __threadfence();
        unsigned my = *((volatile unsigned*)&g_bar_gen);
        unsigned old = atomicAdd(&g_bar_cnt, 1);
        if (old == nblocks - 1) {
            atomicExch(&g_bar_cnt, 0);
            __threadfence();
            atomicAdd(&g_bar_gen, 1);
        } else {
            while (*((volatile unsigned*)&g_bar_gen) == my) __nanosleep(64);
        }
        __threadfence();
    }
    __syncthreads();
}

// ---------------- tf32 helpers ----------------------------------------------
__device__ __forceinline__ uint32_t f2tf32(float f) {
    uint32_t u;
    asm("cvt.rna.tf32.f32 %0, %1;" : "=r"(u) : "f"(f));
    return u;
}

__device__ __forceinline__ void mma_tf32(float* c, uint32_t a0, uint32_t a1,
                                         uint32_t a2, uint32_t a3,
                                         uint32_t b0, uint32_t b1) {
    asm volatile("mma.sync.aligned.m16n8k8.row.col.f32.tf32.tf32.f32 "
                 "{%0,%1,%2,%3}, {%4,%5,%6,%7}, {%8,%9}, {%0,%1,%2,%3};"
                 : "+f"(c[0]), "+f"(c[1]), "+f"(c[2]), "+f"(c[3])
                 : "r"(a0), "r"(a1), "r"(a2), "r"(a3), "r"(b0), "r"(b1));
}

// ---------------- the whole network in one persistent kernel ----------------
__global__ void __launch_bounds__(256)
sage_mega(const float* __restrict__ x,
          const float* __restrict__ w0, const float* __restrict__ b0,
          const float* __restrict__ w1, const float* __restrict__ b1,
          const int* __restrict__ es0, const int* __restrict__ ed0,
          const int* __restrict__ es1, const int* __restrict__ ed1,
          float* __restrict__ out, int E0, int E1) {
    extern __shared__ uint32_t smu[];
    uint32_t* wsh  = smu;                  // W^T tf32: [64][WSTRIDE]
    uint32_t* insh = smu + D * WSTRIDE;    // A tf32:   [128][INSTRIDE]
    float* hsh = reinterpret_cast<float*>(insh);

    const int tid  = threadIdx.x;
    const int wid  = tid >> 5;
    const int lane = tid & 31;
    const int gid  = lane >> 2;
    const int qid  = lane & 3;
    const unsigned nb = gridDim.x;
    const int gstride = nb * 256;
    const int gt = blockIdx.x * 256 + tid;

    int* c0   = g_cnti;
    int* c1   = g_cnti + N1C;

    // ===== P0: build (L0 slots by dst, L1 counts by dst, L1 slots by src) ====
    for (int e = gt; e < E0 + 2 * E1; e += gstride) {
        if (e < E0) {
            int d = ed0[e];
            int p = atomicAdd(&c0[d], 1);
            if (p < CAP) g_slots0[d * CAP + p] = es0[e];
        } else if (e < E0 + E1) {
            atomicAdd(&c1[ed1[e - E0]], 1);
        } else {
            int i = e - E0 - E1;
            int s = es1[i];
            int p = atomicAdd(&g_c1s[s], 1);
            if (p < CAP1) g_slots1s[s * CAP1 + p] = ed1[i];
        }
    }
    grid_barrier(nb);

    // ===== P1: layer-0 gather + mean (16 lanes/target), resets c0 ===========
    {
        const int l = gt & 15;
        const float4* base = reinterpret_cast<const float4*>(x);
        for (int g = gt >> 4; g < N1C; g += gstride >> 4) {
            int deg = c0[g];
            int m = min(deg, CAP);
            const int* sl = g_slots0 + (size_t)g * CAP;
            float4 acc = make_float4(0.f, 0.f, 0.f, 0.f);
            int e = 0;
            for (; e + 8 <= m; e += 8) {
                int4 ia = *reinterpret_cast<const int4*>(sl + e);
                int4 ib = *reinterpret_cast<const int4*>(sl + e + 4);
                float4 v0 = base[(size_t)ia.x * 16 + l];
                float4 v1 = base[(size_t)ia.y * 16 + l];
                float4 v2 = base[(size_t)ia.z * 16 + l];
                float4 v3 = base[(size_t)ia.w * 16 + l];
                float4 v4 = base[(size_t)ib.x * 16 + l];
                float4 v5 = base[(size_t)ib.y * 16 + l];
                float4 v6 = base[(size_t)ib.z * 16 + l];
                float4 v7 = base[(size_t)ib.w * 16 + l];
                acc.x += ((v0.x + v1.x) + (v2.x + v3.x)) + ((v4.x + v5.x) + (v6.x + v7.x));
                acc.y += ((v0.y + v1.y) + (v2.y + v3.y)) + ((v4.y + v5.y) + (v6.y + v7.y));
                acc.z += ((v0.z + v1.z) + (v2.z + v3.z)) + ((v4.z + v5.z) + (v6.z + v7.z));
                acc.w += ((v0.w + v1.w) + (v2.w + v3.w)) + ((v4.w + v5.w) + (v6.w + v7.w));
            }
            for (; e < m; e++) {
                float4 v = base[(size_t)sl[e] * 16 + l];
                acc.x += v.x; acc.y += v.y; acc.z += v.z; acc.w += v.w;
            }
            float scl = 1.0f / fmaxf((float)deg, 1.0f);
            acc.x *= scl; acc.y *= scl; acc.z *= scl; acc.w *= scl;
            reinterpret_cast<float4*>(g_agg0)[(size_t)g * 16 + l] = acc;
            if (l == 0) c0[g] = 0;
        }
    }
    grid_barrier(nb);

    // ===== P2: gemm0 ([x|agg0]@W0+b0, relu) + fused L1 scatter, resets c1s ===
    // stage W0^T once per CTA
    for (int i = tid; i < TWO_D * 16; i += 256) {
        int k = i >> 4;
        int l = i & 15;
        float4 v = reinterpret_cast<const float4*>(w0)[i];
        wsh[(l * 4 + 0) * WSTRIDE + k] = f2tf32(v.x);
        wsh[(l * 4 + 1) * WSTRIDE + k] = f2tf32(v.y);
        wsh[(l * 4 + 2) * WSTRIDE + k] = f2tf32(v.z);
        wsh[(l * 4 + 3) * WSTRIDE + k] = f2tf32(v.w);
    }
    for (int tile = blockIdx.x; tile < NTILES0; tile += nb) {
        const int row0 = tile * 128;
        const float4* sbase = reinterpret_cast<const float4*>(x);
        const float4* abase = reinterpret_cast<const float4*>(g_agg0);
        for (int i = tid; i < 128 * 16; i += 256) {
            int r = i >> 4;
            int l = i & 15;
            size_t gi = (size_t)(row0 + r) * 16 + l;
            float4 s = sbase[gi];
            float4 a = abase[gi];
            uint32_t* dst = insh + r * INSTRIDE + l * 4;
            dst[0] = f2tf32(s.x); dst[1] = f2tf32(s.y);
            dst[2] = f2tf32(s.z); dst[3] = f2tf32(s.w);
            uint32_t* dst2 = dst + D;
            dst2[0] = f2tf32(a.x); dst2[1] = f2tf32(a.y);
            dst2[2] = f2tf32(a.z); dst2[3] = f2tf32(a.w);
        }
        __syncthreads();

        const uint32_t* a_base = insh + (wid * 16 + gid) * INSTRIDE + qid;
        const uint32_t* b_base = wsh + gid * WSTRIDE + qid;
        float c[8][4] = {};
        #pragma unroll
        for (int k0 = 0; k0 < TWO_D; k0 += 8) {
            uint32_t a0 = a_base[k0];
            uint32_t a1 = a_base[8 * INSTRIDE + k0];
            uint32_t a2 = a_base[k0 + 4];
            uint32_t a3 = a_base[8 * INSTRIDE + k0 + 4];
            #pragma unroll
            for (int nt = 0; nt < 8; nt++) {
                uint32_t bb0 = b_base[nt * 8 * WSTRIDE + k0];
                uint32_t bb1 = b_base[nt * 8 * WSTRIDE + k0 + 4];
                mma_tf32(c[nt], a0, a1, a2, a3, bb0, bb1);
            }
        }
        __syncthreads();   // A reads done; insh reusable as hsh

        int rloc = wid * 16 + gid;
        int row = row0 + rloc;
        #pragma unroll
        for (int nt = 0; nt < 8; nt++) {
            int col = nt * 8 + qid * 2;
            float2 bv = *reinterpret_cast<const float2*>(b0 + col);
            float2 r01 = make_float2(fmaxf(c[nt][0] + bv.x, 0.f),
                                     fmaxf(c[nt][1] + bv.y, 0.f));
            float2 r23 = make_float2(fmaxf(c[nt][2] + bv.x, 0.f),
                                     fmaxf(c[nt][3] + bv.y, 0.f));
            *reinterpret_cast<float2*>(hsh + rloc * HSTRIDE + col) = r01;
            *reinterpret_cast<float2*>(hsh + (rloc + 8) * HSTRIDE + col) = r23;
            if (row < N2C)
                *reinterpret_cast<float2*>(g_h1 + (size_t)row * D + col) = r01;
            if (row + 8 < N2C)
                *reinterpret_cast<float2*>(g_h1 + (size_t)(row + 8) * D + col) = r23;
        }
        __syncthreads();

        // fused L1 scatter from smem h tile
        const int sub = lane >> 4;
        const int l = lane & 15;
        for (int j = 0; j < 16; j++) {
            int r = wid * 16 + j;
            int R = row0 + r;
            int deg = min(g_c1s[R], CAP1);
            const float4 v = *reinterpret_cast<const float4*>(hsh + r * HSTRIDE + l * 4);
            for (int e = sub; e < deg; e += 2) {
                int d = g_slots1s[R * CAP1 + e];
                float* dst = g_agg1 + (size_t)d * D + l * 4;
                asm volatile("red.global.add.v4.f32 [%0], {%1,%2,%3,%4};"
                             :: "l"(dst), "f"(v.x), "f"(v.y), "f"(v.z), "f"(v.w)
                             : "memory");
            }
            if (lane == 0) g_c1s[R] = 0;
        }
        __syncthreads();   // scatter reads of hsh done before next tile staging
    }
    grid_barrier(nb);

    // ===== P3: gemm1 ([h1|agg1/c1]@W1+b1) on CTAs 0..15; restores zeros =====
    if (blockIdx.x < NTILES1) {
        const int row0 = blockIdx.x * 128;
        for (int i = tid; i < TWO_D * 16; i += 256) {
            int k = i >> 4;
            int l = i & 15;
            float4 v = reinterpret_cast<const float4*>(w1)[i];
            wsh[(l * 4 + 0) * WSTRIDE + k] = f2tf32(v.x);
            wsh[(l * 4 + 1) * WSTRIDE + k] = f2tf32(v.y);
            wsh[(l * 4 + 2) * WSTRIDE + k] = f2tf32(v.z);
            wsh[(l * 4 + 3) * WSTRIDE + k] = f2tf32(v.w);
        }
        const float4* sbase = reinterpret_cast<const float4*>(g_h1);
        float4* abase = reinterpret_cast<float4*>(g_agg1);
        for (int i = tid; i < 128 * 16; i += 256) {
            int r = i >> 4;
            int l = i & 15;
            int row = row0 + r;
            size_t gi = (size_t)row * 16 + l;
            float4 s = sbase[gi];
            float4 a = abase[gi];
            float scl = 1.0f / fmaxf((float)c1[row], 1.0f);
            a.x *= scl; a.y *= scl; a.z *= scl; a.w *= scl;
            uint32_t* dst = insh + r * INSTRIDE + l * 4;
            dst[0] = f2tf32(s.x); dst[1] = f2tf32(s.y);
            dst[2] = f2tf32(s.z); dst[3] = f2tf32(s.w);
            uint32_t* dst2 = dst + D;
            dst2[0] = f2tf32(a.x); dst2[1] = f2tf32(a.y);
            dst2[2] = f2tf32(a.z); dst2[3] = f2tf32(a.w);
        }
        __syncthreads();

        // restore zero-invariants
        for (int i = tid; i < 128 * 16; i += 256) {
            int r = i >> 4;
            int l = i & 15;
            abase[(size_t)(row0 + r) * 16 + l] = make_float4(0.f, 0.f, 0.f, 0.f);
        }
        if (tid < 128) c1[row0 + tid] = 0;

        const uint32_t* a_base = insh + (wid * 16 + gid) * INSTRIDE + qid;
        const uint32_t* b_base = wsh + gid * WSTRIDE + qid;
        float c[8][4] = {};
        #pragma unroll
        for (int k0 = 0; k0 < TWO_D; k0 += 8) {
            uint32_t a0 = a_base[k0];
            uint32_t a1 = a_base[8 * INSTRIDE + k0];
            uint32_t a2 = a_base[k0 + 4];
            uint32_t a3 = a_base[8 * INSTRIDE + k0 + 4];
            #pragma unroll
            for (int nt = 0; nt < 8; nt++) {
                uint32_t bb0 = b_base[nt * 8 * WSTRIDE + k0];
                uint32_t bb1 = b_base[nt * 8 * WSTRIDE + k0 + 4];
                mma_tf32(c[nt], a0, a1, a2, a3, bb0, bb1);
            }
        }

        int row = row0 + wid * 16 + gid;
        #pragma unroll
        for (int nt = 0; nt < 8; nt++) {
            int col = nt * 8 + qid * 2;
            float2 bv = *reinterpret_cast<const float2*>(b1 + col);
            float2 r01 = make_float2(c[nt][0] + bv.x, c[nt][1] + bv.y);
            float2 r23 = make_float2(c[nt][2] + bv.x, c[nt][3] + bv.y);
            *reinterpret_cast<float2*>(out + (size_t)row * D + col) = r01;
            *reinterpret_cast<float2*>(out + (size_t)(row + 8) * D + col) = r23;
        }
    }
}

static const int SMEM_MMA = (D * WSTRIDE + 128 * INSTRIDE) * (int)sizeof(uint32_t);

// ---------------- launch ---------------------------------------------------
extern "C" void kernel_launch(void* const* d_in, const int* in_sizes, int n_in,
                              void* d_out, int out_size) {
    const float* x         = (const float*)d_in[0];
    const float* w0        = (const float*)d_in[1];
    const float* b0        = (const float*)d_in[2];
    const float* w1        = (const float*)d_in[3];
    const float* b1        = (const float*)d_in[4];
    const int*   edge_src0 = (const int*)d_in[5];
    const int*   edge_dst0 = (const int*)d_in[6];
    const int*   edge_src1 = (const int*)d_in[7];
    const int*   edge_dst1 = (const int*)d_in[8];
    const int E0 = in_sizes[5];
    const int E1 = in_sizes[7];

    cudaFuncSetAttribute(sage_mega,
                         cudaFuncAttributeMaxDynamicSharedMemorySize, SMEM_MMA);

    int sm_count = 148, per_sm = 1;
    cudaDeviceGetAttribute(&sm_count, cudaDevAttrMultiProcessorCount, 0);
    cudaOccupancyMaxActiveBlocksPerMultiprocessor(&per_sm, sage_mega, 256,
                                                  SMEM_MMA);
    if (per_sm < 1) per_sm = 1;
    if (per_sm > 2) per_sm = 2;
    int grid = sm_count * per_sm;

    sage_mega<<<grid, 256, SMEM_MMA>>>(x, w0, b0, w1, b1,
                                       edge_src0, edge_dst0,
                                       edge_src1, edge_dst1,
                                       (float*)d_out, E0, E1);
}

// round 10
// speedup vs baseline: 1.3624x; 1.2707x over previous
#include <cuda_runtime.h>
#include <cstdint>

#define N1C 43008
#define N2C 2048
#define D 64
#define TWO_D 128
#define CAP 96
#define CAP1 16
#define WSTRIDE 132
#define INSTRIDE 132
#define HSTRIDE 68
#define NTILES0 (N1C / 128)   // 336
#define NTILES1 (N2C / 128)   // 16

// ---------------- device-global scratch ------------------------------------
__device__ float g_agg0[N1C * D];
__device__ float g_h1[N2C * D];
__device__ float g_agg1[N2C * D];        // zero-invariant (gemm1 restores)
__device__ int   g_cnti[N1C + N2C];      // c0 | c1 ; restored in-kernel
__device__ int   g_c1s[N1C];             // L1 out-degree by src; gemm0 restores
__device__ int   g_slots0[N1C * CAP];
__device__ int   g_slots1s[N1C * CAP1];
__device__ unsigned g_bar_cnt = 0;
__device__ unsigned g_bar_gen = 0;       // monotonic across replays

// ---------------- software grid barrier -------------------------------------
__device__ __forceinline__ void grid_barrier(unsigned nblocks) {
    __syncthreads();
    if (threadIdx.x == 0) {
        __threadfence();
        unsigned my = *((volatile unsigned*)&g_bar_gen);
        unsigned old = atomicAdd(&g_bar_cnt, 1);
        if (old == nblocks - 1) {
            atomicExch(&g_bar_cnt, 0);
            __threadfence();
            atomicAdd(&g_bar_gen, 1);
        } else {
            while (*((volatile unsigned*)&g_bar_gen) == my) __nanosleep(64);
        }
        __threadfence();
    }
    __syncthreads();
}

// ---------------- Kernel A: persistent fill + gather0 (zero smem) -----------
__global__ void __launch_bounds__(256)
build_gather_kernel(const float* __restrict__ x,
                    const int* __restrict__ es0, const int* __restrict__ ed0,
                    const int* __restrict__ es1, const int* __restrict__ ed1,
                    int E0, int E1) {
    const int tid = threadIdx.x;
    const unsigned nb = gridDim.x;
    const int gstride = nb * 256;
    const int gt = blockIdx.x * 256 + tid;
    int* c0 = g_cnti;
    int* c1 = g_cnti + N1C;

    // ---- P0: build all adjacency structures in one edge-parallel pass ----
    for (int e = gt; e < E0 + 2 * E1; e += gstride) {
        if (e < E0) {
            int d = ed0[e];
            int p = atomicAdd(&c0[d], 1);
            if (p < CAP) g_slots0[d * CAP + p] = es0[e];
        } else if (e < E0 + E1) {
            atomicAdd(&c1[ed1[e - E0]], 1);
        } else {
            int i = e - E0 - E1;
            int s = es1[i];
            int p = atomicAdd(&g_c1s[s], 1);
            if (p < CAP1) g_slots1s[s * CAP1 + p] = ed1[i];
        }
    }
    grid_barrier(nb);

    // ---- P1: layer-0 gather + mean (16 lanes/target), resets c0 ----
    const int l = gt & 15;
    const int tgt_stride = gstride >> 4;
    const float4* base = reinterpret_cast<const float4*>(x);
    for (int g = gt >> 4; g < N1C; g += tgt_stride) {
        int deg = c0[g];
        int m = min(deg, CAP);
        const int* sl = g_slots0 + (size_t)g * CAP;
        float4 acc = make_float4(0.f, 0.f, 0.f, 0.f);
        int e = 0;
        for (; e + 8 <= m; e += 8) {
            int4 ia = *reinterpret_cast<const int4*>(sl + e);
            int4 ib = *reinterpret_cast<const int4*>(sl + e + 4);
            float4 v0 = base[(size_t)ia.x * 16 + l];
            float4 v1 = base[(size_t)ia.y * 16 + l];
            float4 v2 = base[(size_t)ia.z * 16 + l];
            float4 v3 = base[(size_t)ia.w * 16 + l];
            float4 v4 = base[(size_t)ib.x * 16 + l];
            float4 v5 = base[(size_t)ib.y * 16 + l];
            float4 v6 = base[(size_t)ib.z * 16 + l];
            float4 v7 = base[(size_t)ib.w * 16 + l];
            acc.x += ((v0.x + v1.x) + (v2.x + v3.x)) + ((v4.x + v5.x) + (v6.x + v7.x));
            acc.y += ((v0.y + v1.y) + (v2.y + v3.y)) + ((v4.y + v5.y) + (v6.y + v7.y));
            acc.z += ((v0.z + v1.z) + (v2.z + v3.z)) + ((v4.z + v5.z) + (v6.z + v7.z));
            acc.w += ((v0.w + v1.w) + (v2.w + v3.w)) + ((v4.w + v5.w) + (v6.w + v7.w));
        }
        for (; e < m; e++) {
            float4 v = base[(size_t)sl[e] * 16 + l];
            acc.x += v.x; acc.y += v.y; acc.z += v.z; acc.w += v.w;
        }
        float scl = 1.0f / fmaxf((float)deg, 1.0f);
        acc.x *= scl; acc.y *= scl; acc.z *= scl; acc.w *= scl;
        reinterpret_cast<float4*>(g_agg0)[(size_t)g * 16 + l] = acc;
        if (l == 0) c0[g] = 0;
    }
}

// ---------------- tf32 helpers ----------------------------------------------
__device__ __forceinline__ uint32_t f2tf32(float f) {
    uint32_t u;
    asm("cvt.rna.tf32.f32 %0, %1;" : "=r"(u) : "f"(f));
    return u;
}

__device__ __forceinline__ void mma_tf32(float* c, uint32_t a0, uint32_t a1,
                                         uint32_t a2, uint32_t a3,
                                         uint32_t b0, uint32_t b1) {
    asm volatile("mma.sync.aligned.m16n8k8.row.col.f32.tf32.tf32.f32 "
                 "{%0,%1,%2,%3}, {%4,%5,%6,%7}, {%8,%9}, {%0,%1,%2,%3};"
                 : "+f"(c[0]), "+f"(c[1]), "+f"(c[2]), "+f"(c[3])
                 : "r"(a0), "r"(a1), "r"(a2), "r"(a3), "r"(b0), "r"(b1));
}

// ---------------- Kernel B: gemm0 + relu + fused L1 scatter -----------------
__global__ void __launch_bounds__(256)
sage_gemm0(const float* __restrict__ self_feat,
           const float* __restrict__ agg,
           const float* __restrict__ w, const float* __restrict__ b,
           float* __restrict__ h1out,
           int* __restrict__ c1s, const int* __restrict__ sl1s,
           float* __restrict__ agg1) {
    extern __shared__ uint32_t smu[];
    uint32_t* wsh  = smu;
    uint32_t* insh = smu + D * WSTRIDE;
    float* hsh = reinterpret_cast<float*>(insh);

    const int tid  = threadIdx.x;
    const int wid  = tid >> 5;
    const int lane = tid & 31;
    const int gid  = lane >> 2;
    const int qid  = lane & 3;
    const int row0 = blockIdx.x * 128;

    for (int i = tid; i < TWO_D * 16; i += 256) {
        int k = i >> 4;
        int l = i & 15;
        float4 v = reinterpret_cast<const float4*>(w)[i];
        wsh[(l * 4 + 0) * WSTRIDE + k] = f2tf32(v.x);
        wsh[(l * 4 + 1) * WSTRIDE + k] = f2tf32(v.y);
        wsh[(l * 4 + 2) * WSTRIDE + k] = f2tf32(v.z);
        wsh[(l * 4 + 3) * WSTRIDE + k] = f2tf32(v.w);
    }

    const float4* sbase = reinterpret_cast<const float4*>(self_feat);
    const float4* abase = reinterpret_cast<const float4*>(agg);
    for (int i = tid; i < 128 * 16; i += 256) {
        int r = i >> 4;
        int l = i & 15;
        size_t gi = (size_t)(row0 + r) * 16 + l;
        float4 s = sbase[gi];
        float4 a = abase[gi];
        uint32_t* dst = insh + r * INSTRIDE + l * 4;
        dst[0] = f2tf32(s.x); dst[1] = f2tf32(s.y);
        dst[2] = f2tf32(s.z); dst[3] = f2tf32(s.w);
        uint32_t* dst2 = dst + D;
        dst2[0] = f2tf32(a.x); dst2[1] = f2tf32(a.y);
        dst2[2] = f2tf32(a.z); dst2[3] = f2tf32(a.w);
    }
    __syncthreads();

    const uint32_t* a_base = insh + (wid * 16 + gid) * INSTRIDE + qid;
    const uint32_t* b_base = wsh + gid * WSTRIDE + qid;
    float c[8][4] = {};
    #pragma unroll
    for (int k0 = 0; k0 < TWO_D; k0 += 8) {
        uint32_t a0 = a_base[k0];
        uint32_t a1 = a_base[8 * INSTRIDE + k0];
        uint32_t a2 = a_base[k0 + 4];
        uint32_t a3 = a_base[8 * INSTRIDE + k0 + 4];
        #pragma unroll
        for (int nt = 0; nt < 8; nt++) {
            uint32_t bb0 = b_base[nt * 8 * WSTRIDE + k0];
            uint32_t bb1 = b_base[nt * 8 * WSTRIDE + k0 + 4];
            mma_tf32(c[nt], a0, a1, a2, a3, bb0, bb1);
        }
    }
    __syncthreads();   // A reads done; insh reusable as hsh

    int rloc = wid * 16 + gid;
    int row = row0 + rloc;
    #pragma unroll
    for (int nt = 0; nt < 8; nt++) {
        int col = nt * 8 + qid * 2;
        float2 bv = *reinterpret_cast<const float2*>(b + col);
        float2 r01 = make_float2(fmaxf(c[nt][0] + bv.x, 0.f),
                                 fmaxf(c[nt][1] + bv.y, 0.f));
        float2 r23 = make_float2(fmaxf(c[nt][2] + bv.x, 0.f),
                                 fmaxf(c[nt][3] + bv.y, 0.f));
        *reinterpret_cast<float2*>(hsh + rloc * HSTRIDE + col) = r01;
        *reinterpret_cast<float2*>(hsh + (rloc + 8) * HSTRIDE + col) = r23;
        if (row < N2C)
            *reinterpret_cast<float2*>(h1out + (size_t)row * D + col) = r01;
        if (row + 8 < N2C)
            *reinterpret_cast<float2*>(h1out + (size_t)(row + 8) * D + col) = r23;
    }
    __syncthreads();

    // fused L1 scatter from smem h tile; warp owns 16 rows, 2 edges/pass
    const int sub = lane >> 4;
    const int l = lane & 15;
    for (int j = 0; j < 16; j++) {
        int r = wid * 16 + j;
        int R = row0 + r;
        int deg = min(c1s[R], CAP1);
        const float4 v = *reinterpret_cast<const float4*>(hsh + r * HSTRIDE + l * 4);
        for (int e = sub; e < deg; e += 2) {
            int d = sl1s[R * CAP1 + e];
            float* dst = agg1 + (size_t)d * D + l * 4;
            asm volatile("red.global.add.v4.f32 [%0], {%1,%2,%3,%4};"
                         :: "l"(dst), "f"(v.x), "f"(v.y), "f"(v.z), "f"(v.w)
                         : "memory");
        }
        if (lane == 0) c1s[R] = 0;
    }
}

// ---------------- Kernel C: gemm1 (mean from c1; restores zeros) ------------
__global__ void __launch_bounds__(256)
sage_gemm1(const float* __restrict__ self_feat,
           float* __restrict__ agg, int* __restrict__ cnti,
           const float* __restrict__ w, const float* __restrict__ b,
           float* __restrict__ out) {
    extern __shared__ uint32_t smu[];
    uint32_t* wsh  = smu;
    uint32_t* insh = smu + D * WSTRIDE;

    const int tid  = threadIdx.x;
    const int wid  = tid >> 5;
    const int lane = tid & 31;
    const int gid  = lane >> 2;
    const int qid  = lane & 3;
    const int row0 = blockIdx.x * 128;

    for (int i = tid; i < TWO_D * 16; i += 256) {
        int k = i >> 4;
        int l = i & 15;
        float4 v = reinterpret_cast<const float4*>(w)[i];
        wsh[(l * 4 + 0) * WSTRIDE + k] = f2tf32(v.x);
        wsh[(l * 4 + 1) * WSTRIDE + k] = f2tf32(v.y);
        wsh[(l * 4 + 2) * WSTRIDE + k] = f2tf32(v.z);
        wsh[(l * 4 + 3) * WSTRIDE + k] = f2tf32(v.w);
    }

    const float4* sbase = reinterpret_cast<const float4*>(self_feat);
    float4* abase = reinterpret_cast<float4*>(agg);
    for (int i = tid; i < 128 * 16; i += 256) {
        int r = i >> 4;
        int l = i & 15;
        int row = row0 + r;
        size_t gi = (size_t)row * 16 + l;
        float4 s = sbase[gi];
        float4 a = abase[gi];
        float scl = 1.0f / fmaxf((float)cnti[row], 1.0f);
        a.x *= scl; a.y *= scl; a.z *= scl; a.w *= scl;
        uint32_t* dst = insh + r * INSTRIDE + l * 4;
        dst[0] = f2tf32(s.x); dst[1] = f2tf32(s.y);
        dst[2] = f2tf32(s.z); dst[3] = f2tf32(s.w);
        uint32_t* dst2 = dst + D;
        dst2[0] = f2tf32(a.x); dst2[1] = f2tf32(a.y);
        dst2[2] = f2tf32(a.z); dst2[3] = f2tf32(a.w);
    }
    __syncthreads();

    for (int i = tid; i < 128 * 16; i += 256) {
        int r = i >> 4;
        int l = i & 15;
        abase[(size_t)(row0 + r) * 16 + l] = make_float4(0.f, 0.f, 0.f, 0.f);
    }
    if (tid < 128) cnti[row0 + tid] = 0;

    const uint32_t* a_base = insh + (wid * 16 + gid) * INSTRIDE + qid;
    const uint32_t* b_base = wsh + gid * WSTRIDE + qid;
    float c[8][4] = {};
    #pragma unroll
    for (int k0 = 0; k0 < TWO_D; k0 += 8) {
        uint32_t a0 = a_base[k0];
        uint32_t a1 = a_base[8 * INSTRIDE + k0];
        uint32_t a2 = a_base[k0 + 4];
        uint32_t a3 = a_base[8 * INSTRIDE + k0 + 4];
        #pragma unroll
        for (int nt = 0; nt < 8; nt++) {
            uint32_t bb0 = b_base[nt * 8 * WSTRIDE + k0];
            uint32_t bb1 = b_base[nt * 8 * WSTRIDE + k0 + 4];
            mma_tf32(c[nt], a0, a1, a2, a3, bb0, bb1);
        }
    }

    int row = row0 + wid * 16 + gid;
    #pragma unroll
    for (int nt = 0; nt < 8; nt++) {
        int col = nt * 8 + qid * 2;
        float2 bv = *reinterpret_cast<const float2*>(b + col);
        float2 r01 = make_float2(c[nt][0] + bv.x, c[nt][1] + bv.y);
        float2 r23 = make_float2(c[nt][2] + bv.x, c[nt][3] + bv.y);
        *reinterpret_cast<float2*>(out + (size_t)row * D + col) = r01;
        *reinterpret_cast<float2*>(out + (size_t)(row + 8) * D + col) = r23;
    }
}

static const int SMEM_MMA = (D * WSTRIDE + 128 * INSTRIDE) * (int)sizeof(uint32_t);

// ---------------- launch ---------------------------------------------------
extern "C" void kernel_launch(void* const* d_in, const int* in_sizes, int n_in,
                              void* d_out, int out_size) {
    const float* x         = (const float*)d_in[0];
    const float* w0        = (const float*)d_in[1];
    const float* b0        = (const float*)d_in[2];
    const float* w1        = (const float*)d_in[3];
    const float* b1        = (const float*)d_in[4];
    const int*   edge_src0 = (const int*)d_in[5];
    const int*   edge_dst0 = (const int*)d_in[6];
    const int*   edge_src1 = (const int*)d_in[7];
    const int*   edge_dst1 = (const int*)d_in[8];
    const int E0 = in_sizes[5];
    const int E1 = in_sizes[7];

    float *agg0, *h1, *agg1;
    int *cnti, *c1s, *slots1s;
    cudaGetSymbolAddress((void**)&agg0,    g_agg0);
    cudaGetSymbolAddress((void**)&h1,      g_h1);
    cudaGetSymbolAddress((void**)&agg1,    g_agg1);
    cudaGetSymbolAddress((void**)&cnti,    g_cnti);
    cudaGetSymbolAddress((void**)&c1s,     g_c1s);
    cudaGetSymbolAddress((void**)&slots1s, g_slots1s);
    int* cnti1 = cnti + N1C;

    static int grid_a = 0;
    if (grid_a == 0) {
        cudaFuncSetAttribute(sage_gemm0,
                             cudaFuncAttributeMaxDynamicSharedMemorySize, SMEM_MMA);
        cudaFuncSetAttribute(sage_gemm1,
                             cudaFuncAttributeMaxDynamicSharedMemorySize, SMEM_MMA);
        int sm_count = 148, per_sm = 1;
        cudaDeviceGetAttribute(&sm_count, cudaDevAttrMultiProcessorCount, 0);
        cudaOccupancyMaxActiveBlocksPerMultiprocessor(&per_sm,
                                                      build_gather_kernel,
                                                      256, 0);
        if (per_sm < 1) per_sm = 1;
        grid_a = sm_count * per_sm;
    }

    // 3 graph nodes
    build_gather_kernel<<<grid_a, 256>>>(x, edge_src0, edge_dst0,
                                         edge_src1, edge_dst1, E0, E1);
    sage_gemm0<<<NTILES0, 256, SMEM_MMA>>>(x, agg0, w0, b0, h1,
                                           c1s, slots1s, agg1);
    sage_gemm1<<<NTILES1, 256, SMEM_MMA>>>(h1, agg1, cnti1, w1, b1,
                                           (float*)d_out);
}